// round 5
// baseline (speedup 1.0000x reference)
#include <cuda_runtime.h>

#define B   64
#define T   100
#define NI  700
#define NH  512
#define NO  20
#define TAUc 0.6f
#define KAPc 0.6f
#define THRc 0.6f
#define LRc  0.05f

// ---------------- persistent device scratch ----------------
__device__ float g_XP  [T*B*NH];   // x @ W1^T, rows m = t*B+b
__device__ float g_TIN [T*B*NI];
__device__ float g_TREC[T*B*NH];
__device__ float g_HT  [T*B*NH];
__device__ float g_Z   [T*B*NH];
__device__ float g_ERR [T*B*NO];
__device__ float g_EF  [T*B*NO];
__device__ float g_A   [T*B*NH];
__device__ float g_gpart[8*512*700];

// ---------------- tin scan (no recurrence) ----------------
__global__ void k_tin(const float* __restrict__ x) {
    int n = blockIdx.x * blockDim.x + threadIdx.x;
    if (n >= B * NI) return;
    int b = n / NI, i = n - b * NI;
    float tv = 0.f;
    for (int t = 0; t < T; t++) {
        tv = TAUc * tv + x[(b * T + t) * NI + i];
        g_TIN[((size_t)t * B + b) * NI + i] = tv;
    }
}

// ---------------- Xproj = X @ W1^T : [6400,512], K=700, 128x128 tiles ----------------
__global__ __launch_bounds__(256) void k_gemmX(const float* __restrict__ x,
                                               const float* __restrict__ w1) {
    __shared__ float As[16][129];
    __shared__ float Bs[16][129];
    int m0 = blockIdx.y * 128, n0 = blockIdx.x * 128;
    int tid = threadIdx.x, tx = tid & 15, ty = tid >> 4;
    float acc[8][8] = {};

    for (int k0 = 0; k0 < NI; k0 += 16) {
#pragma unroll
        for (int rep = 0; rep < 2; rep++) {
            int f = tid + rep * 256;
            int mm = f >> 2, kq = f & 3;
            int kg = k0 + kq * 4;
            {
                int m = m0 + mm, t = m >> 6, b = m & 63;
                const float* xp = &x[((size_t)b * T + t) * NI + kg];
                float4 v;
                if (kg + 3 < NI) v = *(const float4*)xp;
                else {
                    v.x = (kg + 0 < NI) ? xp[0] : 0.f;
                    v.y = (kg + 1 < NI) ? xp[1] : 0.f;
                    v.z = (kg + 2 < NI) ? xp[2] : 0.f;
                    v.w = (kg + 3 < NI) ? xp[3] : 0.f;
                }
                As[kq * 4 + 0][mm] = v.x; As[kq * 4 + 1][mm] = v.y;
                As[kq * 4 + 2][mm] = v.z; As[kq * 4 + 3][mm] = v.w;
            }
            {
                int n = n0 + mm;
                const float* wp = &w1[(size_t)n * NI + kg];
                float4 v;
                if (kg + 3 < NI) v = *(const float4*)wp;
                else {
                    v.x = (kg + 0 < NI) ? wp[0] : 0.f;
                    v.y = (kg + 1 < NI) ? wp[1] : 0.f;
                    v.z = (kg + 2 < NI) ? wp[2] : 0.f;
                    v.w = (kg + 3 < NI) ? wp[3] : 0.f;
                }
                Bs[kq * 4 + 0][mm] = v.x; Bs[kq * 4 + 1][mm] = v.y;
                Bs[kq * 4 + 2][mm] = v.z; Bs[kq * 4 + 3][mm] = v.w;
            }
        }
        __syncthreads();
#pragma unroll
        for (int k = 0; k < 16; k++) {
            float a[8], bb[8];
#pragma unroll
            for (int i = 0; i < 4; i++) {
                a[i]      = As[k][ty * 4 + i];
                a[4 + i]  = As[k][64 + ty * 4 + i];
                bb[i]     = Bs[k][tx * 4 + i];
                bb[4 + i] = Bs[k][64 + tx * 4 + i];
            }
#pragma unroll
            for (int i = 0; i < 8; i++)
#pragma unroll
                for (int j = 0; j < 8; j++) acc[i][j] += a[i] * bb[j];
        }
        __syncthreads();
    }
#pragma unroll
    for (int i = 0; i < 8; i++) {
        int m = m0 + ((i < 4) ? ty * 4 + i : 64 + ty * 4 + (i - 4));
#pragma unroll
        for (int j = 0; j < 8; j++) {
            int n = n0 + ((j < 4) ? tx * 4 + j : 64 + tx * 4 + (j - 4));
            g_XP[(size_t)m * NH + n] = acc[i][j];
        }
    }
}

// ---------------- forward: one block per sample, no grid barrier ----------------
// threads 0..511: neuron r (state in regs). warps 16..19: output LIF (5 outs each),
// pipelined one step behind. z_{t-1} in smem; spike gather from L2-resident wrec.
__global__ __launch_bounds__(640) void k_forward(const float* __restrict__ wrec,
                                                 const float* __restrict__ wout,
                                                 const float* __restrict__ label,
                                                 float* __restrict__ out) {
    __shared__ float zsh[NH];
    __shared__ unsigned zmask[16];
    __shared__ float ws[NO * NH];   // 40KB
    int b = blockIdx.x;
    int tid = threadIdx.x, lane = tid & 31, w = tid >> 5;
    bool is_n = (tid < NH);
    int r = tid;
    int ow = w - 16;                // 0..3 for output warps

    for (int i = tid; i < NO * NH; i += 640) ws[i] = wout[i];
    if (tid < NH) zsh[tid] = 0.f;
    if (tid < 16) zmask[tid] = 0u;
    __syncthreads();

    float hm = 0.f, tr = 0.f, zs = 0.f;
    float om[5] = {}, os[5] = {};

    auto do_out = [&](int tp) {
#pragma unroll
        for (int q = 0; q < 5; q++) {
            int o = ow * 5 + q;
            float s = 0.f;
#pragma unroll
            for (int c = 0; c < 16; c++)
                s += zsh[c * 32 + lane] * ws[o * NH + c * 32 + lane];
#pragma unroll
            for (int off = 16; off; off >>= 1) s += __shfl_xor_sync(0xffffffffu, s, off);
            om[q] = TAUc * om[q] * (1.f - os[q]) + s;
            os[q] = (om[q] >= THRc) ? 1.f : 0.f;
            if (lane == 0) {
                float err = os[q] - label[((size_t)b * T + tp) * NO + o];
                out[((size_t)b * T + tp) * NO + o] = os[q];
                g_ERR[((size_t)tp * B + b) * NO + o] = err;
            }
        }
    };

    for (int t = 0; t < T; t++) {
        float z = 0.f, ht = 0.f;
        if (is_n) {
            float xp = __ldg(&g_XP[((size_t)t * B + b) * NH + r]);
            float acc = 0.f;
#pragma unroll
            for (int c = 0; c < 16; c++) {
                unsigned m = zmask[c];
                while (m) {
                    int j = c * 32 + (__ffs(m) - 1);
                    m &= m - 1;
                    acc += __ldg(&wrec[(size_t)j * NH + r]);
                }
            }
            hm = TAUc * hm * (1.f - zs) + xp + acc;
            z  = (hm >= THRc) ? 1.f : 0.f;
            ht = TAUc * fmaxf(0.f, 1.f - fabsf((hm - THRc) * (1.f / THRc)));
            tr = TAUc * tr + zs;
        } else if (t > 0) {
            do_out(t - 1);          // overlaps with neuron work; reads zsh = z_{t-1}
        }
        __syncthreads();            // all zsh readers done
        if (is_n) {
            zsh[r] = z;
            unsigned m = __ballot_sync(0xffffffffu, z != 0.f);
            if (lane == 0) zmask[w] = m;
            size_t o = ((size_t)t * B + b) * NH + r;
            g_Z[o] = z; g_HT[o] = ht; g_TREC[o] = tr;
            zs = z;
        }
        __syncthreads();            // zsh/zmask published
    }
    if (!is_n) do_out(T - 1);       // epilogue: output step for final z
}

// ---------------- reverse-time kappa filter of err ----------------
__global__ void k_rev() {
    int n = blockIdx.x * 256 + threadIdx.x;
    if (n >= B * NO) return;
    float ef = 0.f;
    for (int t = T - 1; t >= 0; t--) {
        ef = g_ERR[(size_t)t * B * NO + n] + KAPc * ef;
        g_EF[(size_t)t * B * NO + n] = ef;
    }
}

// ---------------- A[m,r] = (EF[m,:] . wout[:,r]) * HT[m,r] ----------------
__global__ void k_A(const float* __restrict__ wout) {
    int gid = blockIdx.x * 256 + threadIdx.x;
    if (gid >= T * B * NH) return;
    int m = gid >> 9;
    int r = gid & (NH - 1);
    const float* ef = g_EF + (size_t)m * NO;
    float L = 0.f;
#pragma unroll
    for (int o = 0; o < NO; o++) L += ef[o] * wout[o * NH + r];
    g_A[gid] = L * g_HT[gid];
}

// ---------------- C = A^T B, 128x128 tiles, split-K partials ----------------
__global__ __launch_bounds__(256) void k_gemm128T(const float* __restrict__ A, int sA,
                                                  const float* __restrict__ Bm, int sB,
                                                  float* __restrict__ Cp,
                                                  int M, int N, int kchunk) {
    __shared__ float As[16][128];
    __shared__ float Bs[16][128];
    int n0 = blockIdx.x * 128, m0 = blockIdx.y * 128;
    int z = blockIdx.z;
    int k0s = z * kchunk;
    int tid = threadIdx.x, tx = tid & 15, ty = tid >> 4;
    float acc[8][8] = {};

    for (int k0 = k0s; k0 < k0s + kchunk; k0 += 16) {
#pragma unroll
        for (int rep = 0; rep < 2; rep++) {
            int f = tid + rep * 256;
            int kk = f >> 5, c4 = (f & 31) * 4;
            *(float4*)&As[kk][c4] = *(const float4*)&A[(size_t)(k0 + kk) * sA + m0 + c4];
            int n = n0 + c4;
            const float* bp = &Bm[(size_t)(k0 + kk) * sB + n];
            float4 bv;
            if (n + 3 < N) bv = *(const float4*)bp;
            else {
                bv.x = (n + 0 < N) ? bp[0] : 0.f;
                bv.y = (n + 1 < N) ? bp[1] : 0.f;
                bv.z = (n + 2 < N) ? bp[2] : 0.f;
                bv.w = (n + 3 < N) ? bp[3] : 0.f;
            }
            *(float4*)&Bs[kk][c4] = bv;
        }
        __syncthreads();
#pragma unroll
        for (int k = 0; k < 16; k++) {
            float a[8], bb[8];
            *(float4*)&a[0]  = *(float4*)&As[k][ty * 4];
            *(float4*)&a[4]  = *(float4*)&As[k][64 + ty * 4];
            *(float4*)&bb[0] = *(float4*)&Bs[k][tx * 4];
            *(float4*)&bb[4] = *(float4*)&Bs[k][64 + tx * 4];
#pragma unroll
            for (int i = 0; i < 8; i++)
#pragma unroll
                for (int j = 0; j < 8; j++) acc[i][j] += a[i] * bb[j];
        }
        __syncthreads();
    }
    float* C = Cp + (size_t)z * M * N;
#pragma unroll
    for (int i = 0; i < 8; i++) {
        int m = m0 + ((i < 4) ? ty * 4 + i : 64 + ty * 4 + (i - 4));
#pragma unroll
        for (int j = 0; j < 8; j++) {
            int n = n0 + ((j < 4) ? tx * 4 + j : 64 + tx * 4 + (j - 4));
            if (n < N) C[(size_t)m * N + n] = acc[i][j];
        }
    }
}

// ---------------- small 64x64 A^T B for go ----------------
__global__ void k_gemmT64(const float* __restrict__ A, int sA,
                          const float* __restrict__ Bm, int sB,
                          float* __restrict__ Cp,
                          int M, int N, int K, int kchunk) {
    __shared__ float As[16][64];
    __shared__ float Bs[16][64];
    int m0 = blockIdx.y * 64, n0 = blockIdx.x * 64;
    int z = blockIdx.z;
    int k0s = z * kchunk;
    int k0e = min(K, k0s + kchunk);
    int tid = threadIdx.x;
    int tx = tid & 15, ty = tid >> 4;
    float acc[4][4] = {};
    for (int k0 = k0s; k0 < k0e; k0 += 16) {
#pragma unroll
        for (int rep = 0; rep < 4; rep++) {
            int e = tid + rep * 256;
            int mm = e & 63, kk = e >> 6;
            int mg = m0 + mm;
            As[kk][mm] = (mg < M) ? A[(size_t)(k0 + kk) * sA + mg] : 0.f;
            int ng = n0 + mm;
            Bs[kk][mm] = (ng < N) ? Bm[(size_t)(k0 + kk) * sB + ng] : 0.f;
        }
        __syncthreads();
#pragma unroll
        for (int k = 0; k < 16; k++) {
            float a[4], bb[4];
#pragma unroll
            for (int i = 0; i < 4; i++) a[i]  = As[k][ty * 4 + i];
#pragma unroll
            for (int j = 0; j < 4; j++) bb[j] = Bs[k][tx * 4 + j];
#pragma unroll
            for (int i = 0; i < 4; i++)
#pragma unroll
                for (int j = 0; j < 4; j++) acc[i][j] += a[i] * bb[j];
        }
        __syncthreads();
    }
    float* C = Cp + (size_t)z * M * N;
#pragma unroll
    for (int i = 0; i < 4; i++) {
        int m = m0 + ty * 4 + i;
        if (m < M) {
#pragma unroll
            for (int j = 0; j < 4; j++) {
                int n = n0 + tx * 4 + j;
                if (n < N) C[(size_t)m * N + n] = acc[i][j];
            }
        }
    }
}

__global__ void k_reduce(const float* __restrict__ Cp, float* __restrict__ out,
                         int MN, int KS) {
    int i = blockIdx.x * 256 + threadIdx.x;
    if (i >= MN) return;
    float s = 0.f;
    for (int z = 0; z < KS; z++) s += Cp[(size_t)z * MN + i];
    out[i] = LRc * s;
}

// ---------------- launch ----------------
extern "C" void kernel_launch(void* const* d_in, const int* in_sizes, int n_in,
                              void* d_out, int out_size) {
    const float* x     = (const float*)d_in[0];
    const float* label = (const float*)d_in[1];
    const float* w1    = (const float*)d_in[3];
    const float* wrec  = (const float*)d_in[4];
    const float* wout  = (const float*)d_in[5];
    float* out = (float*)d_out;
    float* gf = out + B * T * NO;          // [NH, NI]
    float* gr = gf + NH * NI;              // [NH, NH]
    float* go = gr + NH * NH;              // [NO, NH]

    float *pA, *pTIN, *pTREC, *pZ, *pEF, *pGP;
    cudaGetSymbolAddress((void**)&pA,    g_A);
    cudaGetSymbolAddress((void**)&pTIN,  g_TIN);
    cudaGetSymbolAddress((void**)&pTREC, g_TREC);
    cudaGetSymbolAddress((void**)&pZ,    g_Z);
    cudaGetSymbolAddress((void**)&pEF,   g_EF);
    cudaGetSymbolAddress((void**)&pGP,   g_gpart);

    k_tin<<<(B * NI + 255) / 256, 256>>>(x);
    k_gemmX<<<dim3(4, 50), 256>>>(x, w1);
    k_forward<<<B, 640>>>(wrec, wout, label, out);
    k_rev<<<5, 256>>>();
    k_A<<<(T * B * NH + 255) / 256, 256>>>(wout);

    // gf = LR * A^T @ TIN   [512 x 700], K=6400, splitK 8
    k_gemm128T<<<dim3(6, 4, 8), 256>>>(pA, NH, pTIN, NI, pGP, NH, NI, 800);
    k_reduce<<<(NH * NI + 255) / 256, 256>>>(pGP, gf, NH * NI, 8);

    // gr = LR * A^T @ TREC  [512 x 512], K=6400, splitK 8
    k_gemm128T<<<dim3(4, 4, 8), 256>>>(pA, NH, pTREC, NH, pGP, NH, NH, 800);
    k_reduce<<<(NH * NH + 255) / 256, 256>>>(pGP, gr, NH * NH, 8);

    // go = LR * EF^T @ Z    [20 x 512], K=6400, splitK 8
    k_gemmT64<<<dim3(8, 1, 8), 256>>>(pEF, NO, pZ, NH, pGP, NO, NH, T * B, 800);
    k_reduce<<<(NO * NH + 255) / 256, 256>>>(pGP, go, NO * NH, 8);
}

// round 6
// speedup vs baseline: 2.3234x; 2.3234x over previous
#include <cuda_runtime.h>

#define B   64
#define T   100
#define NI  700
#define NH  512
#define NO  20
#define TAUc 0.6f
#define KAPc 0.6f
#define THRc 0.6f
#define LRc  0.05f

// ---------------- persistent device scratch ----------------
__device__ float g_XP  [T*B*NH];   // x @ W1^T, rows m = t*B+b
__device__ float g_TIN [T*B*NI];
__device__ float g_TREC[T*B*NH];
__device__ float g_HT  [T*B*NH];
__device__ float g_Z   [T*B*NH];
__device__ float g_EF  [T*B*NO];
__device__ float g_A   [T*B*NH];
__device__ float g_gpart[8*512*700];

// forward smem layout (dynamic): ws[NO*NH] | zsh[NH] | errh[T*NO] | list[NH] | wcnt[16]
#define FWD_SMEM ((NO*NH + NH + T*NO + 16) * 4 + NH * 4)

// ---------------- tin scan (no recurrence) ----------------
__global__ void k_tin(const float* __restrict__ x) {
    int n = blockIdx.x * blockDim.x + threadIdx.x;
    if (n >= B * NI) return;
    int b = n / NI, i = n - b * NI;
    float tv = 0.f;
    for (int t = 0; t < T; t++) {
        tv = TAUc * tv + x[(b * T + t) * NI + i];
        g_TIN[((size_t)t * B + b) * NI + i] = tv;
    }
}

// ---------------- Xproj = X @ W1^T : [6400,512], K=700, 128x128 tiles ----------------
__global__ __launch_bounds__(256) void k_gemmX(const float* __restrict__ x,
                                               const float* __restrict__ w1) {
    __shared__ float As[16][129];
    __shared__ float Bs[16][129];
    int m0 = blockIdx.y * 128, n0 = blockIdx.x * 128;
    int tid = threadIdx.x, tx = tid & 15, ty = tid >> 4;
    float acc[8][8] = {};

    for (int k0 = 0; k0 < NI; k0 += 16) {
#pragma unroll
        for (int rep = 0; rep < 2; rep++) {
            int f = tid + rep * 256;
            int mm = f >> 2, kq = f & 3;
            int kg = k0 + kq * 4;
            {
                int m = m0 + mm, t = m >> 6, b = m & 63;
                const float* xp = &x[((size_t)b * T + t) * NI + kg];
                float4 v;
                if (kg + 3 < NI) v = *(const float4*)xp;
                else {
                    v.x = (kg + 0 < NI) ? xp[0] : 0.f;
                    v.y = (kg + 1 < NI) ? xp[1] : 0.f;
                    v.z = (kg + 2 < NI) ? xp[2] : 0.f;
                    v.w = (kg + 3 < NI) ? xp[3] : 0.f;
                }
                As[kq * 4 + 0][mm] = v.x; As[kq * 4 + 1][mm] = v.y;
                As[kq * 4 + 2][mm] = v.z; As[kq * 4 + 3][mm] = v.w;
            }
            {
                int n = n0 + mm;
                const float* wp = &w1[(size_t)n * NI + kg];
                float4 v;
                if (kg + 3 < NI) v = *(const float4*)wp;
                else {
                    v.x = (kg + 0 < NI) ? wp[0] : 0.f;
                    v.y = (kg + 1 < NI) ? wp[1] : 0.f;
                    v.z = (kg + 2 < NI) ? wp[2] : 0.f;
                    v.w = (kg + 3 < NI) ? wp[3] : 0.f;
                }
                Bs[kq * 4 + 0][mm] = v.x; Bs[kq * 4 + 1][mm] = v.y;
                Bs[kq * 4 + 2][mm] = v.z; Bs[kq * 4 + 3][mm] = v.w;
            }
        }
        __syncthreads();
#pragma unroll
        for (int k = 0; k < 16; k++) {
            float a[8], bb[8];
#pragma unroll
            for (int i = 0; i < 4; i++) {
                a[i]      = As[k][ty * 4 + i];
                a[4 + i]  = As[k][64 + ty * 4 + i];
                bb[i]     = Bs[k][tx * 4 + i];
                bb[4 + i] = Bs[k][64 + tx * 4 + i];
            }
#pragma unroll
            for (int i = 0; i < 8; i++)
#pragma unroll
                for (int j = 0; j < 8; j++) acc[i][j] += a[i] * bb[j];
        }
        __syncthreads();
    }
#pragma unroll
    for (int i = 0; i < 8; i++) {
        int m = m0 + ((i < 4) ? ty * 4 + i : 64 + ty * 4 + (i - 4));
#pragma unroll
        for (int j = 0; j < 8; j++) {
            int n = n0 + ((j < 4) ? tx * 4 + j : 64 + tx * 4 + (j - 4));
            g_XP[(size_t)m * NH + n] = acc[i][j];
        }
    }
}

// ---------------- forward: one block per sample, compacted spike list ----------------
// threads 0..511: neuron tid. warps 16..19: output LIF, one step behind.
// Active-index list rebuilt each step (deterministic order). Gather = batched
// independent LDGs from L2-resident wrec (MLP=16). Reverse kappa filter fused.
__global__ __launch_bounds__(640) void k_forward(const float* __restrict__ wrec,
                                                 const float* __restrict__ wout,
                                                 const float* __restrict__ label,
                                                 float* __restrict__ out) {
    extern __shared__ float sm[];
    float* ws   = sm;                       // NO*NH
    float* zsh  = ws + NO * NH;             // NH
    float* errh = zsh + NH;                 // T*NO
    int*   list = (int*)(errh + T * NO);    // NH
    int*   wcnt = list + NH;                // 16

    int b = blockIdx.x;
    int tid = threadIdx.x, lane = tid & 31, w = tid >> 5;
    bool is_n = (tid < NH);
    int ow = w - 16;

    for (int i = tid; i < NO * NH; i += 640) ws[i] = wout[i];
    if (tid < NH) zsh[tid] = 0.f;
    if (tid < 16) wcnt[tid] = 0;
    __syncthreads();

    float hm = 0.f, tr = 0.f, zs = 0.f;
    float om[5] = {}, os[5] = {};
    int nact = 0;

    auto do_out = [&](int tp) {
#pragma unroll
        for (int q = 0; q < 5; q++) {
            int o = ow * 5 + q;
            float s = 0.f;
#pragma unroll
            for (int c = 0; c < 16; c++)
                s += zsh[c * 32 + lane] * ws[o * NH + c * 32 + lane];
#pragma unroll
            for (int off = 16; off; off >>= 1) s += __shfl_xor_sync(0xffffffffu, s, off);
            om[q] = TAUc * om[q] * (1.f - os[q]) + s;
            os[q] = (om[q] >= THRc) ? 1.f : 0.f;
            if (lane == 0) {
                out[((size_t)b * T + tp) * NO + o] = os[q];
                errh[tp * NO + o] = os[q] - label[((size_t)b * T + tp) * NO + o];
            }
        }
    };

    for (int t = 0; t < T; t++) {
        float z = 0.f, ht = 0.f;
        if (is_n) {
            float xp = __ldg(&g_XP[((size_t)t * B + b) * NH + tid]);
            float acc = 0.f;
            for (int i = 0; i < nact; i += 16) {
                float v[16];
#pragma unroll
                for (int u = 0; u < 16; u++) {
                    int ix = i + u;
                    v[u] = (ix < nact) ? __ldg(&wrec[(size_t)list[ix] * NH + tid]) : 0.f;
                }
#pragma unroll
                for (int u = 0; u < 16; u++) acc += v[u];
            }
            hm = TAUc * hm * (1.f - zs) + xp + acc;
            z  = (hm >= THRc) ? 1.f : 0.f;
            ht = TAUc * fmaxf(0.f, 1.f - fabsf((hm - THRc) * (1.f / THRc)));
            tr = TAUc * tr + zs;
            size_t o = ((size_t)t * B + b) * NH + tid;
            g_Z[o] = z; g_HT[o] = ht; g_TREC[o] = tr;
            zs = z;
        } else if (t > 0) {
            do_out(t - 1);              // reads zsh = z_{t-1}
        }
        __syncthreads();                // zsh/list consumers done

        unsigned m = 0;
        if (is_n) {
            zsh[tid] = z;
            m = __ballot_sync(0xffffffffu, z != 0.f);
            if (lane == 0) wcnt[w] = __popc(m);
        }
        __syncthreads();                // wcnt/zsh published

        if (is_n) {
            int basew = 0, tot = 0;
#pragma unroll
            for (int c = 0; c < 16; c++) {
                int cc = wcnt[c];
                tot += cc;
                if (c < w) basew += cc;
            }
            nact = tot;
            if (z != 0.f)
                list[basew + __popc(m & ((1u << lane) - 1u))] = tid;
        }
        __syncthreads();                // list ready for next step's gather
    }
    if (!is_n) do_out(T - 1);
    __syncthreads();

    // fused reverse kappa filter (err history in smem)
    if (tid < NO) {
        float ef = 0.f;
        for (int t = T - 1; t >= 0; t--) {
            ef = errh[t * NO + tid] + KAPc * ef;
            g_EF[((size_t)t * B + b) * NO + tid] = ef;
        }
    }
}

// ---------------- A[m,r] = (EF[m,:] . wout[:,r]) * HT[m,r] ----------------
__global__ void k_A(const float* __restrict__ wout) {
    int gid = blockIdx.x * 256 + threadIdx.x;
    if (gid >= T * B * NH) return;
    int m = gid >> 9;
    int r = gid & (NH - 1);
    const float* ef = g_EF + (size_t)m * NO;
    float L = 0.f;
#pragma unroll
    for (int o = 0; o < NO; o++) L += ef[o] * wout[o * NH + r];
    g_A[gid] = L * g_HT[gid];
}

// ---------------- C = A^T B, 128x128 tiles, split-K partials ----------------
__global__ __launch_bounds__(256) void k_gemm128T(const float* __restrict__ A, int sA,
                                                  const float* __restrict__ Bm, int sB,
                                                  float* __restrict__ Cp,
                                                  int M, int N, int kchunk) {
    __shared__ float As[16][128];
    __shared__ float Bs[16][128];
    int n0 = blockIdx.x * 128, m0 = blockIdx.y * 128;
    int z = blockIdx.z;
    int k0s = z * kchunk;
    int tid = threadIdx.x, tx = tid & 15, ty = tid >> 4;
    float acc[8][8] = {};

    for (int k0 = k0s; k0 < k0s + kchunk; k0 += 16) {
#pragma unroll
        for (int rep = 0; rep < 2; rep++) {
            int f = tid + rep * 256;
            int kk = f >> 5, c4 = (f & 31) * 4;
            *(float4*)&As[kk][c4] = *(const float4*)&A[(size_t)(k0 + kk) * sA + m0 + c4];
            int n = n0 + c4;
            const float* bp = &Bm[(size_t)(k0 + kk) * sB + n];
            float4 bv;
            if (n + 3 < N) bv = *(const float4*)bp;
            else {
                bv.x = (n + 0 < N) ? bp[0] : 0.f;
                bv.y = (n + 1 < N) ? bp[1] : 0.f;
                bv.z = (n + 2 < N) ? bp[2] : 0.f;
                bv.w = (n + 3 < N) ? bp[3] : 0.f;
            }
            *(float4*)&Bs[kk][c4] = bv;
        }
        __syncthreads();
#pragma unroll
        for (int k = 0; k < 16; k++) {
            float a[8], bb[8];
            *(float4*)&a[0]  = *(float4*)&As[k][ty * 4];
            *(float4*)&a[4]  = *(float4*)&As[k][64 + ty * 4];
            *(float4*)&bb[0] = *(float4*)&Bs[k][tx * 4];
            *(float4*)&bb[4] = *(float4*)&Bs[k][64 + tx * 4];
#pragma unroll
            for (int i = 0; i < 8; i++)
#pragma unroll
                for (int j = 0; j < 8; j++) acc[i][j] += a[i] * bb[j];
        }
        __syncthreads();
    }
    float* C = Cp + (size_t)z * M * N;
#pragma unroll
    for (int i = 0; i < 8; i++) {
        int m = m0 + ((i < 4) ? ty * 4 + i : 64 + ty * 4 + (i - 4));
#pragma unroll
        for (int j = 0; j < 8; j++) {
            int n = n0 + ((j < 4) ? tx * 4 + j : 64 + tx * 4 + (j - 4));
            if (n < N) C[(size_t)m * N + n] = acc[i][j];
        }
    }
}

// ---------------- small 64x64 A^T B for go ----------------
__global__ void k_gemmT64(const float* __restrict__ A, int sA,
                          const float* __restrict__ Bm, int sB,
                          float* __restrict__ Cp,
                          int M, int N, int K, int kchunk) {
    __shared__ float As[16][64];
    __shared__ float Bs[16][64];
    int m0 = blockIdx.y * 64, n0 = blockIdx.x * 64;
    int z = blockIdx.z;
    int k0s = z * kchunk;
    int k0e = min(K, k0s + kchunk);
    int tid = threadIdx.x;
    int tx = tid & 15, ty = tid >> 4;
    float acc[4][4] = {};
    for (int k0 = k0s; k0 < k0e; k0 += 16) {
#pragma unroll
        for (int rep = 0; rep < 4; rep++) {
            int e = tid + rep * 256;
            int mm = e & 63, kk = e >> 6;
            int mg = m0 + mm;
            As[kk][mm] = (mg < M) ? A[(size_t)(k0 + kk) * sA + mg] : 0.f;
            int ng = n0 + mm;
            Bs[kk][mm] = (ng < N) ? Bm[(size_t)(k0 + kk) * sB + ng] : 0.f;
        }
        __syncthreads();
#pragma unroll
        for (int k = 0; k < 16; k++) {
            float a[4], bb[4];
#pragma unroll
            for (int i = 0; i < 4; i++) a[i]  = As[k][ty * 4 + i];
#pragma unroll
            for (int j = 0; j < 4; j++) bb[j] = Bs[k][tx * 4 + j];
#pragma unroll
            for (int i = 0; i < 4; i++)
#pragma unroll
                for (int j = 0; j < 4; j++) acc[i][j] += a[i] * bb[j];
        }
        __syncthreads();
    }
    float* C = Cp + (size_t)z * M * N;
#pragma unroll
    for (int i = 0; i < 4; i++) {
        int m = m0 + ty * 4 + i;
        if (m < M) {
#pragma unroll
            for (int j = 0; j < 4; j++) {
                int n = n0 + tx * 4 + j;
                if (n < N) C[(size_t)m * N + n] = acc[i][j];
            }
        }
    }
}

__global__ void k_reduce(const float* __restrict__ Cp, float* __restrict__ out,
                         int MN, int KS) {
    int i = blockIdx.x * 256 + threadIdx.x;
    if (i >= MN) return;
    float s = 0.f;
    for (int z = 0; z < KS; z++) s += Cp[(size_t)z * MN + i];
    out[i] = LRc * s;
}

// ---------------- launch ----------------
extern "C" void kernel_launch(void* const* d_in, const int* in_sizes, int n_in,
                              void* d_out, int out_size) {
    const float* x     = (const float*)d_in[0];
    const float* label = (const float*)d_in[1];
    const float* w1    = (const float*)d_in[3];
    const float* wrec  = (const float*)d_in[4];
    const float* wout  = (const float*)d_in[5];
    float* out = (float*)d_out;
    float* gf = out + B * T * NO;          // [NH, NI]
    float* gr = gf + NH * NI;              // [NH, NH]
    float* go = gr + NH * NH;              // [NO, NH]

    cudaFuncSetAttribute(k_forward, cudaFuncAttributeMaxDynamicSharedMemorySize, FWD_SMEM);

    float *pA, *pTIN, *pTREC, *pZ, *pEF, *pGP;
    cudaGetSymbolAddress((void**)&pA,    g_A);
    cudaGetSymbolAddress((void**)&pTIN,  g_TIN);
    cudaGetSymbolAddress((void**)&pTREC, g_TREC);
    cudaGetSymbolAddress((void**)&pZ,    g_Z);
    cudaGetSymbolAddress((void**)&pEF,   g_EF);
    cudaGetSymbolAddress((void**)&pGP,   g_gpart);

    k_tin<<<(B * NI + 255) / 256, 256>>>(x);
    k_gemmX<<<dim3(4, 50), 256>>>(x, w1);
    k_forward<<<B, 640, FWD_SMEM>>>(wrec, wout, label, out);
    k_A<<<(T * B * NH + 255) / 256, 256>>>(wout);

    // gf = LR * A^T @ TIN   [512 x 700], K=6400, splitK 8
    k_gemm128T<<<dim3(6, 4, 8), 256>>>(pA, NH, pTIN, NI, pGP, NH, NI, 800);
    k_reduce<<<(NH * NI + 255) / 256, 256>>>(pGP, gf, NH * NI, 8);

    // gr = LR * A^T @ TREC  [512 x 512], K=6400, splitK 8
    k_gemm128T<<<dim3(4, 4, 8), 256>>>(pA, NH, pTREC, NH, pGP, NH, NH, 800);
    k_reduce<<<(NH * NH + 255) / 256, 256>>>(pGP, gr, NH * NH, 8);

    // go = LR * EF^T @ Z    [20 x 512], K=6400, splitK 8
    k_gemmT64<<<dim3(8, 1, 8), 256>>>(pEF, NO, pZ, NH, pGP, NO, NH, T * B, 800);
    k_reduce<<<(NO * NH + 255) / 256, 256>>>(pGP, go, NO * NH, 8);
}